// round 14
// baseline (speedup 1.0000x reference)
#include <cuda_runtime.h>
#include <cuda_fp16.h>
#include <cstdint>

// Matern-3/2 Gram via fp16 2-term-split HMMA (mma.sync m16n8k16) + fused epilogue.
//   Xc = [hi(X) | lo(X)], Zc = [hi(Z) | lo(Z)]  (K=128, fp16)
//   Diagonal GEMM gives dot = hi_x·hi_z + lo_x·lo_z; the MISSING cross terms
//   are ~2^-11 per k (fp16 11-bit mantissa) -> rel_err ~4e-5, well under 1e-3.
//   (R12 failed because bf16's 2^-8 mantissa made the missing cross ~1.3e-3.)
//   out = s^2 (1+v) exp(-v), v = sqrt(3)*sqrt(max(x2+z2-2dot,1e-12))/ls
// R13: CTA 128x128, 256 thr, 8 warps (warp 32x64), 2 CTAs/SM, 2-stage cp.async.

#define D_DIM 64
#define KC    128
#define NMAX  8192
#define MMAX  4096

#define ROWB  256           // bytes per row in gmem scratch (128 fp16)
#define LDSW  144           // padded smem row bytes per stage (128 data + 16)
#define STG   (128 * LDSW)  // 18432 B per operand per stage

__device__ __align__(16) __half g_Xc[NMAX * KC];   // 2 MB
__device__ __align__(16) __half g_Zc[MMAX * KC];   // 1 MB
__device__ float g_x2[NMAX];
__device__ float g_z2[MMAX];

// smem layout (74752 B total -> 2 CTAs/SM)
#define SM_XN 0                      // 128 floats
#define SM_ZN 512                    // 128 floats
#define SM_A  1024                   // 2 stages x 18432
#define SM_B  (SM_A + 2 * STG)
#define SM_TOTAL (SM_B + 2 * STG)    // 74752 B

__device__ __forceinline__ uint32_t s2u(const void* p) {
    uint32_t a;
    asm("{ .reg .u64 t; cvta.to.shared.u64 t, %1; cvt.u32.u64 %0, t; }"
        : "=r"(a) : "l"(p));
    return a;
}
__device__ __forceinline__ float fsqrt_ap(float x) {
    float r; asm("sqrt.approx.f32 %0, %1;" : "=f"(r) : "f"(x)); return r;
}
__device__ __forceinline__ float fex2(float x) {
    float r; asm("ex2.approx.f32 %0, %1;" : "=f"(r) : "f"(x)); return r;
}

#define CP16(dst, src)                                                        \
    asm volatile("cp.async.cg.shared.global [%0], [%1], 16;"                  \
                 :: "r"(dst), "l"(src) : "memory")

#define LDSM_X4(r0, r1, r2, r3, addr)                                         \
    asm volatile("ldmatrix.sync.aligned.m8n8.x4.shared.b16 {%0,%1,%2,%3}, [%4];" \
                 : "=r"(r0), "=r"(r1), "=r"(r2), "=r"(r3) : "r"(addr))

#define MMA16816(c, a, b0v, b1v)                                              \
    asm volatile("mma.sync.aligned.m16n8k16.row.col.f32.f16.f16.f32 "         \
                 "{%0,%1,%2,%3}, {%4,%5,%6,%7}, {%8,%9}, {%0,%1,%2,%3};"      \
                 : "+f"((c)[0]), "+f"((c)[1]), "+f"((c)[2]), "+f"((c)[3])     \
                 : "r"((a)[0]), "r"((a)[1]), "r"((a)[2]), "r"((a)[3]),        \
                   "r"(b0v), "r"(b1v))

// ---- prep: warp per row; lane owns 2 k-positions (coalesced) ----
__global__ void convert_kernel(const float* __restrict__ X,
                               const float* __restrict__ Z, int N, int M) {
    int t = blockIdx.x * blockDim.x + threadIdx.x;
    int row = t >> 5, lane = t & 31;
    if (row >= N + M) return;
    const float* src; __half* dst; float* nd;
    if (row < N) { src = X + (size_t)row * D_DIM; dst = g_Xc + (size_t)row * KC; nd = &g_x2[row]; }
    else { int r = row - N; src = Z + (size_t)r * D_DIM; dst = g_Zc + (size_t)r * KC; nd = &g_z2[r]; }

    int k = lane * 2;
    float2 v = *(const float2*)(src + k);
    float s = fmaf(v.x, v.x, v.y * v.y);
#pragma unroll
    for (int d = 16; d > 0; d >>= 1)
        s += __shfl_xor_sync(0xffffffffu, s, d);

    __half hx = __float2half_rn(v.x);
    __half hy = __float2half_rn(v.y);
    __half2 hi; hi.x = hx; hi.y = hy;
    __half2 lo;
    lo.x = __float2half_rn(v.x - __half2float(hx));
    lo.y = __float2half_rn(v.y - __half2float(hy));
    *(__half2*)(dst + k) = hi;         // K[0:64)   = hi
    *(__half2*)(dst + 64 + k) = lo;    // K[64:128) = lo
    if (lane == 0) *nd = s;
}

// ---- one K=64 stage: 4 k-steps of 16, warp tile 32x64 ----
__device__ __forceinline__ void stage_mma(uint32_t aBase, uint32_t bBase,
                                          const uint32_t* a_off,
                                          const uint32_t* b_off,
                                          float acc[2][8][4]) {
#pragma unroll
    for (int ks = 0; ks < 4; ++ks) {
        uint32_t a[2][4];
#pragma unroll
        for (int mt = 0; mt < 2; ++mt)
            LDSM_X4(a[mt][0], a[mt][1], a[mt][2], a[mt][3],
                    aBase + a_off[mt] + ks * 32);
#pragma unroll
        for (int p = 0; p < 4; ++p) {
            uint32_t b[4];
            LDSM_X4(b[0], b[1], b[2], b[3], bBase + b_off[p] + ks * 32);
#pragma unroll
            for (int mt = 0; mt < 2; ++mt) {
                MMA16816(acc[mt][2 * p], a[mt], b[0], b[1]);
                MMA16816(acc[mt][2 * p + 1], a[mt], b[2], b[3]);
            }
        }
    }
}

// ---- main: 128x128 CTA tile, 8 warps (4m x 2n), warp = 32x64, 2 CTAs/SM ----
__global__ __launch_bounds__(256, 2)
void matern_hmma_kernel(const float* __restrict__ sigma,
                        const float* __restrict__ lengthscale,
                        float* __restrict__ out, int M) {
    extern __shared__ char smem[];
    const uint32_t sb = s2u(smem);
    const int tid = threadIdx.x;
    const int lane = tid & 31, wid = tid >> 5;
    const int wm = wid & 3;      // 4 m-blocks of 32 rows
    const int wn = wid >> 2;     // 2 n-blocks of 64 cols
    const int bn = blockIdx.y, bm = blockIdx.x;

    // row norms into smem
    if (tid < 128)
        ((float*)(smem + SM_XN))[tid] = g_x2[bn * 128 + tid];
    else
        ((float*)(smem + SM_ZN))[tid - 128] = g_z2[bm * 128 + (tid - 128)];

    // 2-stage cp.async tile loads (K chunks of 64 fp16 = 128B per row)
    {
        const char* As = (const char*)g_Xc + (size_t)(bn * 128) * ROWB;
        const char* Bs = (const char*)g_Zc + (size_t)(bm * 128) * ROWB;
#pragma unroll
        for (int s2 = 0; s2 < 2; ++s2) {
#pragma unroll
            for (int it = 0; it < 8; ++it) {
                if (it < 4) {                   // A: 1024 x 16B chunks
                    int i = tid + it * 256;
                    int row = i >> 3, c = i & 7;
                    CP16(sb + SM_A + s2 * STG + row * LDSW + c * 16,
                         As + (size_t)row * ROWB + s2 * 128 + c * 16);
                } else {                        // B: 1024 x 16B chunks
                    int j = tid + (it - 4) * 256;
                    int row = j >> 3, c = j & 7;
                    CP16(sb + SM_B + s2 * STG + row * LDSW + c * 16,
                         Bs + (size_t)row * ROWB + s2 * 128 + c * 16);
                }
            }
            asm volatile("cp.async.commit_group;" ::: "memory");
        }
    }

    // per-lane ldmatrix offsets (within a stage)
    const int l8 = lane & 7, sel = lane >> 3;
    uint32_t a_off[2], b_off[4];
#pragma unroll
    for (int mt = 0; mt < 2; ++mt) {
        int row = wm * 32 + mt * 16 + ((sel & 1) << 3) + l8;
        a_off[mt] = row * LDSW + ((sel >> 1) << 4);
    }
#pragma unroll
    for (int p = 0; p < 4; ++p) {
        int n = wn * 64 + p * 16 + ((sel >> 1) << 3) + l8;
        b_off[p] = n * LDSW + ((sel & 1) << 4);
    }

    float acc[2][8][4];
#pragma unroll
    for (int mt = 0; mt < 2; ++mt)
#pragma unroll
        for (int nt = 0; nt < 8; ++nt)
#pragma unroll
            for (int q = 0; q < 4; ++q) acc[mt][nt][q] = 0.0f;

    asm volatile("cp.async.wait_group 1;" ::: "memory");
    __syncthreads();
    stage_mma(sb + SM_A, sb + SM_B, a_off, b_off, acc);

    asm volatile("cp.async.wait_group 0;" ::: "memory");
    __syncthreads();
    stage_mma(sb + SM_A + STG, sb + SM_B + STG, a_off, b_off, acc);

    // ---- fused Matern epilogue ----
    const float ls = *lengthscale;
    const float sg = *sigma;
    const float cc = 1.7320508075688772f / ls;
    const float s2v = sg * sg;
    const float NL2E = -1.4426950408889634f;

    const int qrow = lane >> 2;          // 0..7
    const int qcol = (lane & 3) << 1;    // 0,2,4,6

    const float* xnS = (const float*)(smem + SM_XN);
    const float* znS = (const float*)(smem + SM_ZN);

    float2 znp[8];
#pragma unroll
    for (int nt = 0; nt < 8; ++nt)
        znp[nt] = *(const float2*)(znS + wn * 64 + nt * 8 + qcol);

#pragma unroll
    for (int mt = 0; mt < 2; ++mt) {
#pragma unroll
        for (int h = 0; h < 2; ++h) {
            const int rloc = wm * 32 + mt * 16 + h * 8 + qrow;
            const float xn = xnS[rloc];
            float* orow = out + (size_t)(bn * 128 + rloc) * M + bm * 128;
#pragma unroll
            for (int nt = 0; nt < 8; ++nt) {
                float d0 = acc[mt][nt][2 * h];
                float d1 = acc[mt][nt][2 * h + 1];
                float sq0 = fmaxf(fmaf(-2.0f, d0, xn + znp[nt].x), 1e-12f);
                float sq1 = fmaxf(fmaf(-2.0f, d1, xn + znp[nt].y), 1e-12f);
                float v0 = cc * fsqrt_ap(sq0);
                float v1 = cc * fsqrt_ap(sq1);
                float e0 = fex2(NL2E * v0);
                float e1 = fex2(NL2E * v1);
                float2 o;
                o.x = s2v * (1.0f + v0) * e0;
                o.y = s2v * (1.0f + v1) * e1;
                *(float2*)(orow + wn * 64 + nt * 8 + qcol) = o;
            }
        }
    }
}

extern "C" void kernel_launch(void* const* d_in, const int* in_sizes, int n_in,
                              void* d_out, int out_size) {
    const float* X = (const float*)d_in[0];
    const float* Z = (const float*)d_in[1];
    const float* sigma = (const float*)d_in[2];
    const float* lengthscale = (const float*)d_in[3];
    float* out = (float*)d_out;

    int N = in_sizes[0] / D_DIM;   // 8192
    int M = in_sizes[1] / D_DIM;   // 4096

    convert_kernel<<<((N + M) * 32 + 255) / 256, 256>>>(X, Z, N, M);

    cudaFuncSetAttribute(matern_hmma_kernel,
                         cudaFuncAttributeMaxDynamicSharedMemorySize, SM_TOTAL);
    dim3 grid(M / 128, N / 128);   // (32, 64)
    matern_hmma_kernel<<<grid, 256, SM_TOTAL>>>(sigma, lengthscale, out, M);
}

// round 15
// speedup vs baseline: 1.2723x; 1.2723x over previous
#include <cuda_runtime.h>
#include <cuda_fp16.h>
#include <cstdint>

// Matern-3/2 Gram via fp16 2-term-split HMMA (mma.sync m16n8k16) + fused epilogue.
//   Xc = [hi(X) | lo(X)], Zc = [hi(Z) | lo(Z)]  (K=128, fp16)
//   Diagonal GEMM -> dot = hi·hi + lo·lo; missing cross terms ~2^-11 per k
//   -> measured rel_err 1.66e-4 (R13), 6x under threshold.
//   out = s^2 (1+v) exp(-v), v = sqrt(3)*sqrt(max(x2+z2-2dot,1e-12))/ls
// R14: R9 geometry (CTA 256x128, 8 warps, warp 64x64 = best LDSM:MMA ratio)
//      + K=128 fp16 split + 2-stage cp.async pipeline.

#define D_DIM 64
#define KC    128
#define NMAX  8192
#define MMAX  4096

#define ROWB  256           // bytes per row in gmem scratch (128 fp16)
#define LDSW  144           // padded smem row bytes per stage (128 data + 16)
#define ASTG  (256 * LDSW)  // 36864 B per A stage
#define BSTG  (128 * LDSW)  // 18432 B per B stage

__device__ __align__(16) __half g_Xc[NMAX * KC];   // 2 MB
__device__ __align__(16) __half g_Zc[MMAX * KC];   // 1 MB
__device__ float g_x2[NMAX];
__device__ float g_z2[MMAX];

// smem layout (112128 B -> 1 CTA/SM)
#define SM_XN 0                      // 256 floats
#define SM_ZN 1024                   // 128 floats
#define SM_A  1536                   // 2 stages x 36864
#define SM_B  (SM_A + 2 * ASTG)      // 2 stages x 18432
#define SM_TOTAL (SM_B + 2 * BSTG)   // 112128 B

__device__ __forceinline__ uint32_t s2u(const void* p) {
    uint32_t a;
    asm("{ .reg .u64 t; cvta.to.shared.u64 t, %1; cvt.u32.u64 %0, t; }"
        : "=r"(a) : "l"(p));
    return a;
}
__device__ __forceinline__ float fsqrt_ap(float x) {
    float r; asm("sqrt.approx.f32 %0, %1;" : "=f"(r) : "f"(x)); return r;
}
__device__ __forceinline__ float fex2(float x) {
    float r; asm("ex2.approx.f32 %0, %1;" : "=f"(r) : "f"(x)); return r;
}

#define CP16(dst, src)                                                        \
    asm volatile("cp.async.cg.shared.global [%0], [%1], 16;"                  \
                 :: "r"(dst), "l"(src) : "memory")

#define LDSM_X4(r0, r1, r2, r3, addr)                                         \
    asm volatile("ldmatrix.sync.aligned.m8n8.x4.shared.b16 {%0,%1,%2,%3}, [%4];" \
                 : "=r"(r0), "=r"(r1), "=r"(r2), "=r"(r3) : "r"(addr))

#define MMA16816(c, a, b0v, b1v)                                              \
    asm volatile("mma.sync.aligned.m16n8k16.row.col.f32.f16.f16.f32 "         \
                 "{%0,%1,%2,%3}, {%4,%5,%6,%7}, {%8,%9}, {%0,%1,%2,%3};"      \
                 : "+f"((c)[0]), "+f"((c)[1]), "+f"((c)[2]), "+f"((c)[3])     \
                 : "r"((a)[0]), "r"((a)[1]), "r"((a)[2]), "r"((a)[3]),        \
                   "r"(b0v), "r"(b1v))

// ---- prep: warp per row; lane owns 2 k-positions (coalesced) ----
__global__ void convert_kernel(const float* __restrict__ X,
                               const float* __restrict__ Z, int N, int M) {
    int t = blockIdx.x * blockDim.x + threadIdx.x;
    int row = t >> 5, lane = t & 31;
    if (row >= N + M) return;
    const float* src; __half* dst; float* nd;
    if (row < N) { src = X + (size_t)row * D_DIM; dst = g_Xc + (size_t)row * KC; nd = &g_x2[row]; }
    else { int r = row - N; src = Z + (size_t)r * D_DIM; dst = g_Zc + (size_t)r * KC; nd = &g_z2[r]; }

    int k = lane * 2;
    float2 v = *(const float2*)(src + k);
    float s = fmaf(v.x, v.x, v.y * v.y);
#pragma unroll
    for (int d = 16; d > 0; d >>= 1)
        s += __shfl_xor_sync(0xffffffffu, s, d);

    __half hx = __float2half_rn(v.x);
    __half hy = __float2half_rn(v.y);
    __half2 hi; hi.x = hx; hi.y = hy;
    __half2 lo;
    lo.x = __float2half_rn(v.x - __half2float(hx));
    lo.y = __float2half_rn(v.y - __half2float(hy));
    *(__half2*)(dst + k) = hi;         // K[0:64)   = hi
    *(__half2*)(dst + 64 + k) = lo;    // K[64:128) = lo
    if (lane == 0) *nd = s;
}

// ---- one K=64 stage: 4 k-steps of 16, warp tile 64x64 ----
__device__ __forceinline__ void stage_mma(uint32_t aBase, uint32_t bBase,
                                          const uint32_t* a_off,
                                          const uint32_t* b_off,
                                          float acc[4][8][4]) {
#pragma unroll
    for (int ks = 0; ks < 4; ++ks) {
        uint32_t a[4][4];
#pragma unroll
        for (int mt = 0; mt < 4; ++mt)
            LDSM_X4(a[mt][0], a[mt][1], a[mt][2], a[mt][3],
                    aBase + a_off[mt] + ks * 32);
#pragma unroll
        for (int p = 0; p < 4; ++p) {
            uint32_t b[4];
            LDSM_X4(b[0], b[1], b[2], b[3], bBase + b_off[p] + ks * 32);
#pragma unroll
            for (int mt = 0; mt < 4; ++mt) {
                MMA16816(acc[mt][2 * p], a[mt], b[0], b[1]);
                MMA16816(acc[mt][2 * p + 1], a[mt], b[2], b[3]);
            }
        }
    }
}

// ---- main: 256x128 CTA tile, 8 warps (4m x 2n), warp = 64x64 ----
__global__ __launch_bounds__(256)
void matern_hmma_kernel(const float* __restrict__ sigma,
                        const float* __restrict__ lengthscale,
                        float* __restrict__ out, int M) {
    extern __shared__ char smem[];
    const uint32_t sb = s2u(smem);
    const int tid = threadIdx.x;
    const int lane = tid & 31, wid = tid >> 5;
    const int wm = wid & 3;      // 4 m-blocks of 64 rows
    const int wn = wid >> 2;     // 2 n-blocks of 64 cols
    const int bn = blockIdx.y, bm = blockIdx.x;

    // row norms into smem
    ((float*)(smem + SM_XN))[tid] = g_x2[bn * 256 + tid];
    if (tid < 128)
        ((float*)(smem + SM_ZN))[tid] = g_z2[bm * 128 + tid];

    // 2-stage cp.async tile loads (K halves of 64 fp16 = 128B per row)
    {
        const char* As = (const char*)g_Xc + (size_t)(bn * 256) * ROWB;
        const char* Bs = (const char*)g_Zc + (size_t)(bm * 128) * ROWB;
#pragma unroll
        for (int s2 = 0; s2 < 2; ++s2) {
#pragma unroll
            for (int it = 0; it < 12; ++it) {
                if (it < 8) {                   // A: 2048 x 16B chunks
                    int i = tid + it * 256;
                    int row = i >> 3, c = i & 7;
                    CP16(sb + SM_A + s2 * ASTG + row * LDSW + c * 16,
                         As + (size_t)row * ROWB + s2 * 128 + c * 16);
                } else {                        // B: 1024 x 16B chunks
                    int j = tid + (it - 8) * 256;
                    int row = j >> 3, c = j & 7;
                    CP16(sb + SM_B + s2 * BSTG + row * LDSW + c * 16,
                         Bs + (size_t)row * ROWB + s2 * 128 + c * 16);
                }
            }
            asm volatile("cp.async.commit_group;" ::: "memory");
        }
    }

    // per-lane ldmatrix offsets (within a stage)
    const int l8 = lane & 7, sel = lane >> 3;
    uint32_t a_off[4], b_off[4];
#pragma unroll
    for (int mt = 0; mt < 4; ++mt) {
        int row = wm * 64 + mt * 16 + ((sel & 1) << 3) + l8;
        a_off[mt] = row * LDSW + ((sel >> 1) << 4);
    }
#pragma unroll
    for (int p = 0; p < 4; ++p) {
        int n = wn * 64 + p * 16 + ((sel >> 1) << 3) + l8;
        b_off[p] = n * LDSW + ((sel & 1) << 4);
    }

    float acc[4][8][4];
#pragma unroll
    for (int mt = 0; mt < 4; ++mt)
#pragma unroll
        for (int nt = 0; nt < 8; ++nt)
#pragma unroll
            for (int q = 0; q < 4; ++q) acc[mt][nt][q] = 0.0f;

    asm volatile("cp.async.wait_group 1;" ::: "memory");
    __syncthreads();
    stage_mma(sb + SM_A, sb + SM_B, a_off, b_off, acc);

    asm volatile("cp.async.wait_group 0;" ::: "memory");
    __syncthreads();
    stage_mma(sb + SM_A + ASTG, sb + SM_B + BSTG, a_off, b_off, acc);

    // ---- fused Matern epilogue ----
    const float ls = *lengthscale;
    const float sg = *sigma;
    const float cc = 1.7320508075688772f / ls;
    const float s2v = sg * sg;
    const float NL2E = -1.4426950408889634f;

    const int qrow = lane >> 2;          // 0..7
    const int qcol = (lane & 3) << 1;    // 0,2,4,6

    const float* xnS = (const float*)(smem + SM_XN);
    const float* znS = (const float*)(smem + SM_ZN);

    float2 znp[8];
#pragma unroll
    for (int nt = 0; nt < 8; ++nt)
        znp[nt] = *(const float2*)(znS + wn * 64 + nt * 8 + qcol);

#pragma unroll
    for (int mt = 0; mt < 4; ++mt) {
#pragma unroll
        for (int h = 0; h < 2; ++h) {
            const int rloc = wm * 64 + mt * 16 + h * 8 + qrow;
            const float xn = xnS[rloc];
            float* orow = out + (size_t)(bn * 256 + rloc) * M + bm * 128;
#pragma unroll
            for (int nt = 0; nt < 8; ++nt) {
                float d0 = acc[mt][nt][2 * h];
                float d1 = acc[mt][nt][2 * h + 1];
                float sq0 = fmaxf(fmaf(-2.0f, d0, xn + znp[nt].x), 1e-12f);
                float sq1 = fmaxf(fmaf(-2.0f, d1, xn + znp[nt].y), 1e-12f);
                float v0 = cc * fsqrt_ap(sq0);
                float v1 = cc * fsqrt_ap(sq1);
                float e0 = fex2(NL2E * v0);
                float e1 = fex2(NL2E * v1);
                float2 o;
                o.x = s2v * (1.0f + v0) * e0;
                o.y = s2v * (1.0f + v1) * e1;
                *(float2*)(orow + wn * 64 + nt * 8 + qcol) = o;
            }
        }
    }
}

extern "C" void kernel_launch(void* const* d_in, const int* in_sizes, int n_in,
                              void* d_out, int out_size) {
    const float* X = (const float*)d_in[0];
    const float* Z = (const float*)d_in[1];
    const float* sigma = (const float*)d_in[2];
    const float* lengthscale = (const float*)d_in[3];
    float* out = (float*)d_out;

    int N = in_sizes[0] / D_DIM;   // 8192
    int M = in_sizes[1] / D_DIM;   // 4096

    convert_kernel<<<((N + M) * 32 + 255) / 256, 256>>>(X, Z, N, M);

    cudaFuncSetAttribute(matern_hmma_kernel,
                         cudaFuncAttributeMaxDynamicSharedMemorySize, SM_TOTAL);
    dim3 grid(M / 128, N / 256);   // (32, 32)
    matern_hmma_kernel<<<grid, 256, SM_TOTAL>>>(sigma, lengthscale, out, M);
}